// round 5
// baseline (speedup 1.0000x reference)
#include <cuda_runtime.h>
#include <cstdint>

#define T_ 12
#define N_ 10000
#define F_ 128
#define H_ 128
#define E_ 320000
#define NH (N_*H_)
#define WSLICE (3*F_*H_)        // 49152 floats per gate weight tensor

// ---------------- scratch (static device memory; no runtime allocation) ----------------
__device__ __align__(16) float g_Tx1[NH];
__device__ __align__(16) float g_Tx2[NH];
__device__ __align__(16) float g_Th1[NH];
__device__ __align__(16) float g_Th2[NH];
__device__ __align__(16) float g_Ts1[NH];
__device__ __align__(16) float g_Ts2[NH];
__device__ __align__(16) float g_h  [NH];
__device__ __align__(16) float g_z  [NH];
__device__ __align__(16) float g_s  [NH];
__device__ __align__(16) float g_W  [6 * WSLICE];   // tf32-rounded weights
__device__ float g_deg[N_];
__device__ int   g_cnt[N_];
__device__ int   g_rowptr[N_ + 1];
__device__ int   g_pos[E_];
__device__ int   g_col[E_];
__device__ float g_val[E_];
__device__ int   g_is64;

__device__ __forceinline__ int edge_at(const void* ei, int idx) {
    if (g_is64) return (int)((const long long*)ei)[idx];
    return ((const int*)ei)[idx];
}

// ---------------- preprocessing ----------------
__global__ void k_init(const int* __restrict__ ei32) {
    int i = blockIdx.x * blockDim.x + threadIdx.x;
    if (i == 0) {
        int any_odd_nonzero = 0;
        for (int k = 1; k < 1024; k += 2) any_odd_nonzero |= (ei32[k] != 0);
        g_is64 = any_odd_nonzero ? 0 : 1;
    }
    if (i < NH) g_h[i] = 0.f;
    if (i < N_) { g_deg[i] = 0.f; g_cnt[i] = 0; }
}

// edge counting + weight tf32 pre-rounding in one launch (grid covers both)
struct W6 { const float* p[6]; };
__global__ void k_count(const void* __restrict__ ei, W6 w) {
    int e = blockIdx.x * blockDim.x + threadIdx.x;
    if (e < 6 * WSLICE) {
        int which = e / WSLICE;
        int off = e - which * WSLICE;
        float v = w.p[which][off];
        uint32_t r;
        asm("cvt.rna.tf32.f32 %0, %1;" : "=r"(r) : "f"(v));
        g_W[e] = __uint_as_float(r);
    }
    if (e >= E_) return;
    int s = edge_at(ei, e);
    int d = edge_at(ei, E_ + e);
    if ((unsigned)s >= N_ || (unsigned)d >= N_) return;
    atomicAdd(&g_deg[s], 1.0f);
    g_pos[e] = atomicAdd(&g_cnt[d], 1);
}

// dinv + exclusive prefix sum (single block, 1024 threads)
__global__ void k_scan() {
    __shared__ int sh[1024];
    int tid = threadIdx.x;
    for (int i = tid; i < N_; i += 1024) {
        float d = g_deg[i];
        g_deg[i] = (d > 0.f) ? rsqrtf(d) : 0.f;
    }
    const int PER = (N_ + 1023) / 1024;
    int base = tid * PER;
    int s = 0;
    for (int i = 0; i < PER; i++) { int ix = base + i; if (ix < N_) s += g_cnt[ix]; }
    sh[tid] = s;
    __syncthreads();
    for (int off = 1; off < 1024; off <<= 1) {
        int v = (tid >= off) ? sh[tid - off] : 0;
        __syncthreads();
        if (tid >= off) sh[tid] += v;
        __syncthreads();
    }
    int run = (tid > 0) ? sh[tid - 1] : 0;
    for (int i = 0; i < PER; i++) {
        int ix = base + i;
        if (ix < N_) { g_rowptr[ix] = run; run += g_cnt[ix]; }
    }
    if (tid == 0) g_rowptr[N_] = sh[1023];
}

__global__ void k_fill(const void* __restrict__ ei) {
    int e = blockIdx.x * blockDim.x + threadIdx.x;
    if (e >= E_) return;
    int s = edge_at(ei, e);
    int d = edge_at(ei, E_ + e);
    if ((unsigned)s >= N_ || (unsigned)d >= N_) return;
    int slot = g_rowptr[d] + g_pos[e];
    g_col[slot] = s;
    g_val[slot] = -g_deg[s] * g_deg[d];
}

// ---------------- graph propagation (dual) ----------------
__global__ void k_prop2(const float* __restrict__ in0, float* __restrict__ out0,
                        const float* __restrict__ sub0,
                        const float* __restrict__ in1, float* __restrict__ out1,
                        const float* __restrict__ sub1, float scale) {
    const float* in  = blockIdx.y ? in1  : in0;
    float*       out = blockIdx.y ? out1 : out0;
    const float* sub = blockIdx.y ? sub1 : sub0;
    if (!in) return;
    int n = blockIdx.x;
    int j = threadIdx.x;
    int e = g_rowptr[n], end = g_rowptr[n + 1];
    float a0 = 0.f, a1 = 0.f, a2 = 0.f, a3 = 0.f;
    for (; e + 4 <= end; e += 4) {
        int   c0 = g_col[e],     c1 = g_col[e + 1], c2 = g_col[e + 2], c3 = g_col[e + 3];
        float w0 = g_val[e],     w1 = g_val[e + 1], w2 = g_val[e + 2], w3 = g_val[e + 3];
        a0 += w0 * __ldg(in + c0 * H_ + j);
        a1 += w1 * __ldg(in + c1 * H_ + j);
        a2 += w2 * __ldg(in + c2 * H_ + j);
        a3 += w3 * __ldg(in + c3 * H_ + j);
    }
    float acc = (a0 + a1) + (a2 + a3);
    for (; e < end; e++) acc += g_val[e] * __ldg(in + g_col[e] * H_ + j);
    float r = scale * acc;
    if (sub) r -= sub[n * H_ + j];
    out[n * H_ + j] = r;
}

// ---------------- tf32 tensor-core GEMMs ----------------
__device__ __forceinline__ float sigf(float x) { return 1.f / (1.f + expf(-x)); }
__device__ __forceinline__ void cp16(uint32_t dst, const void* src) {
    asm volatile("cp.async.cg.shared.global [%0], [%1], 16;\n" :: "r"(dst), "l"(src));
}
__device__ __forceinline__ uint32_t f2tf32(float v) {
    uint32_t r;
    asm("cvt.rna.tf32.f32 %0, %1;" : "=r"(r) : "f"(v));
    return r;
}
__device__ __forceinline__ void mma_tf32(float c[4], const uint32_t a[4], const uint32_t b[2]) {
    asm volatile(
        "mma.sync.aligned.m16n8k8.row.col.f32.tf32.tf32.f32 "
        "{%0,%1,%2,%3}, {%4,%5,%6,%7}, {%8,%9}, {%0,%1,%2,%3};\n"
        : "+f"(c[0]), "+f"(c[1]), "+f"(c[2]), "+f"(c[3])
        : "r"(a[0]), "r"(a[1]), "r"(a[2]), "r"(a[3]), "r"(b[0]), "r"(b[1]));
}

#define AS_STRIDE 36   // 32 + 4 pad: a-frag bank = 4g+tig, conflict-free
#define BS_STRIDE 72   // 64 + 8 pad: b-frag bank = 8tig+g, conflict-free
#define AS_WORDS (64 * AS_STRIDE)   // 2304
#define BS_WORDS (32 * BS_STRIDE)   // 2304

// ---- fused z + r GEMM: shares A tiles & fragments across two gate pipelines ----
// vz = sum A_p Bz_p + bz; vr = sum A_p Br_p + br; z=sigmoid(vz); s=h*sigmoid(vr)
struct GZR {
    const float* A[6];
    const float* Bz[6];
    const float* Br[6];
    const float* bz0; const float* bz1;
    const float* br0; const float* br1;
    const float* h;
    float* zout; float* sout;
};

__global__ __launch_bounds__(128) void k_gemm_zr(GZR P) {
    extern __shared__ float sm[];
    float* As = sm;                        // 2 bufs x 2304
    float* Bz = sm + 2 * AS_WORDS;         // 2 bufs x 2304
    float* Br = sm + 2 * AS_WORDS + 2 * BS_WORDS;

    const int tid  = threadIdx.x;
    const int wid  = tid >> 5, lane = tid & 31;
    const int g    = lane >> 2, tig = lane & 3;
    const int wm   = wid >> 1, wn = wid & 1;
    const int bm   = blockIdx.x * 64;
    const int bn   = blockIdx.y * 64;

    float cz[2][4][4], cr[2][4][4];
#pragma unroll
    for (int im = 0; im < 2; im++)
#pragma unroll
        for (int it = 0; it < 4; it++)
#pragma unroll
            for (int q = 0; q < 4; q++) { cz[im][it][q] = 0.f; cr[im][it][q] = 0.f; }

    auto issue = [&](int s) {
        int pr = s >> 2, ch = s & 3, buf = s & 1;
        uint32_t sA = (uint32_t)__cvta_generic_to_shared(As + buf * AS_WORDS);
        uint32_t sZ = (uint32_t)__cvta_generic_to_shared(Bz + buf * BS_WORDS);
        uint32_t sR = (uint32_t)__cvta_generic_to_shared(Br + buf * BS_WORDS);
        const float* Ap = P.A[pr];
        const float* Zp = P.Bz[pr];
        const float* Rp = P.Br[pr];
#pragma unroll
        for (int i = 0; i < 4; i++) {               // A: 64x32 = 512 float4
            int fi = tid + 128 * i;
            int row = fi >> 3, c4 = fi & 7;
            int ar = bm + row; if (ar > N_ - 1) ar = N_ - 1;
            cp16(sA + (uint32_t)(row * AS_STRIDE + c4 * 4) * 4,
                 Ap + ar * F_ + ch * 32 + c4 * 4);
        }
#pragma unroll
        for (int i = 0; i < 4; i++) {               // Bz: 32x64 = 512 float4
            int fi = tid + 128 * i;
            int row = fi >> 4, c4 = fi & 15;
            cp16(sZ + (uint32_t)(row * BS_STRIDE + c4 * 4) * 4,
                 Zp + (ch * 32 + row) * H_ + bn + c4 * 4);
        }
#pragma unroll
        for (int i = 0; i < 4; i++) {               // Br: 32x64 = 512 float4
            int fi = tid + 128 * i;
            int row = fi >> 4, c4 = fi & 15;
            cp16(sR + (uint32_t)(row * BS_STRIDE + c4 * 4) * 4,
                 Rp + (ch * 32 + row) * H_ + bn + c4 * 4);
        }
        asm volatile("cp.async.commit_group;\n" ::: "memory");
    };

    issue(0);
#pragma unroll 1
    for (int s = 0; s < 24; s++) {                  // 6 pairs x 4 k-chunks of 32
        if (s + 1 < 24) {
            issue(s + 1);
            asm volatile("cp.async.wait_group 1;\n" ::: "memory");
        } else {
            asm volatile("cp.async.wait_group 0;\n" ::: "memory");
        }
        __syncthreads();
        const float* As_ = As + (s & 1) * AS_WORDS;
        const float* Bz_ = Bz + (s & 1) * BS_WORDS;
        const float* Br_ = Br + (s & 1) * BS_WORDS;
#pragma unroll
        for (int ks = 0; ks < 4; ks++) {
            const int k = ks * 8;
            uint32_t a[2][4];
#pragma unroll
            for (int im = 0; im < 2; im++) {
                int r0 = wm * 32 + im * 16 + g;
                a[im][0] = f2tf32(As_[r0 * AS_STRIDE + k + tig]);
                a[im][1] = f2tf32(As_[(r0 + 8) * AS_STRIDE + k + tig]);
                a[im][2] = f2tf32(As_[r0 * AS_STRIDE + k + tig + 4]);
                a[im][3] = f2tf32(As_[(r0 + 8) * AS_STRIDE + k + tig + 4]);
            }
            uint32_t bz[4][2], br[4][2];
#pragma unroll
            for (int it = 0; it < 4; it++) {
                int cb = wn * 32 + it * 8 + g;
                bz[it][0] = __float_as_uint(Bz_[(k + tig) * BS_STRIDE + cb]);
                bz[it][1] = __float_as_uint(Bz_[(k + tig + 4) * BS_STRIDE + cb]);
                br[it][0] = __float_as_uint(Br_[(k + tig) * BS_STRIDE + cb]);
                br[it][1] = __float_as_uint(Br_[(k + tig + 4) * BS_STRIDE + cb]);
            }
#pragma unroll
            for (int im = 0; im < 2; im++)
#pragma unroll
                for (int it = 0; it < 4; it++) {
                    mma_tf32(cz[im][it], a[im], bz[it]);
                    mma_tf32(cr[im][it], a[im], br[it]);
                }
        }
        __syncthreads();
    }

    // epilogue: z = sigmoid(vz); s = h * sigmoid(vr)
#pragma unroll
    for (int im = 0; im < 2; im++) {
        int rbase = bm + wm * 32 + im * 16 + g;
#pragma unroll
        for (int half = 0; half < 2; half++) {
            int row = rbase + half * 8;
            if (row >= N_) continue;
#pragma unroll
            for (int it = 0; it < 4; it++) {
#pragma unroll
                for (int q = 0; q < 2; q++) {
                    int col = bn + wn * 32 + it * 8 + 2 * tig + q;
                    int idx = row * H_ + col;
                    float vz = cz[im][it][half * 2 + q] + __ldg(P.bz0 + col) + __ldg(P.bz1 + col);
                    float vr = cr[im][it][half * 2 + q] + __ldg(P.br0 + col) + __ldg(P.br1 + col);
                    P.zout[idx] = sigf(vz);
                    P.sout[idx] = P.h[idx] * sigf(vr);
                }
            }
        }
    }
}

// ---- h-update GEMM: h = z*h + (1-z)*tanh(sum A_p B_p + b) ----
struct GP {
    const float* A[6];
    const float* B[6];
    const float* b0; const float* b1;
    const float* h;  const float* z;
    float* out;
};

__global__ __launch_bounds__(128) void k_gemm_h(GP P) {
    __shared__ float As[2][AS_WORDS];
    __shared__ float Bs[2][BS_WORDS];

    const int tid  = threadIdx.x;
    const int wid  = tid >> 5, lane = tid & 31;
    const int g    = lane >> 2, tig = lane & 3;
    const int wm   = wid >> 1, wn = wid & 1;
    const int bm   = blockIdx.x * 64;
    const int bn   = blockIdx.y * 64;

    float c[2][4][4];
#pragma unroll
    for (int im = 0; im < 2; im++)
#pragma unroll
        for (int it = 0; it < 4; it++)
#pragma unroll
            for (int q = 0; q < 4; q++) c[im][it][q] = 0.f;

    auto issue = [&](int s) {
        int pr = s >> 2, ch = s & 3, buf = s & 1;
        uint32_t sA = (uint32_t)__cvta_generic_to_shared(&As[buf][0]);
        uint32_t sB = (uint32_t)__cvta_generic_to_shared(&Bs[buf][0]);
        const float* Ap = P.A[pr];
        const float* Bp = P.B[pr];
#pragma unroll
        for (int i = 0; i < 4; i++) {
            int fi = tid + 128 * i;
            int row = fi >> 3, c4 = fi & 7;
            int ar = bm + row; if (ar > N_ - 1) ar = N_ - 1;
            cp16(sA + (uint32_t)(row * AS_STRIDE + c4 * 4) * 4,
                 Ap + ar * F_ + ch * 32 + c4 * 4);
        }
#pragma unroll
        for (int i = 0; i < 4; i++) {
            int fi = tid + 128 * i;
            int row = fi >> 4, c4 = fi & 15;
            cp16(sB + (uint32_t)(row * BS_STRIDE + c4 * 4) * 4,
                 Bp + (ch * 32 + row) * H_ + bn + c4 * 4);
        }
        asm volatile("cp.async.commit_group;\n" ::: "memory");
    };

    issue(0);
#pragma unroll 1
    for (int s = 0; s < 24; s++) {
        if (s + 1 < 24) {
            issue(s + 1);
            asm volatile("cp.async.wait_group 1;\n" ::: "memory");
        } else {
            asm volatile("cp.async.wait_group 0;\n" ::: "memory");
        }
        __syncthreads();
        const float* As_ = As[s & 1];
        const float* Bs_ = Bs[s & 1];
#pragma unroll
        for (int ks = 0; ks < 4; ks++) {
            const int k = ks * 8;
            uint32_t a[2][4];
#pragma unroll
            for (int im = 0; im < 2; im++) {
                int r0 = wm * 32 + im * 16 + g;
                a[im][0] = f2tf32(As_[r0 * AS_STRIDE + k + tig]);
                a[im][1] = f2tf32(As_[(r0 + 8) * AS_STRIDE + k + tig]);
                a[im][2] = f2tf32(As_[r0 * AS_STRIDE + k + tig + 4]);
                a[im][3] = f2tf32(As_[(r0 + 8) * AS_STRIDE + k + tig + 4]);
            }
            uint32_t b[4][2];
#pragma unroll
            for (int it = 0; it < 4; it++) {
                int cb = wn * 32 + it * 8 + g;
                b[it][0] = __float_as_uint(Bs_[(k + tig) * BS_STRIDE + cb]);
                b[it][1] = __float_as_uint(Bs_[(k + tig + 4) * BS_STRIDE + cb]);
            }
#pragma unroll
            for (int im = 0; im < 2; im++)
#pragma unroll
                for (int it = 0; it < 4; it++) mma_tf32(c[im][it], a[im], b[it]);
        }
        __syncthreads();
    }

#pragma unroll
    for (int im = 0; im < 2; im++) {
        int rbase = bm + wm * 32 + im * 16 + g;
#pragma unroll
        for (int half = 0; half < 2; half++) {
            int row = rbase + half * 8;
            if (row >= N_) continue;
#pragma unroll
            for (int it = 0; it < 4; it++) {
#pragma unroll
                for (int q = 0; q < 2; q++) {
                    int col = bn + wn * 32 + it * 8 + 2 * tig + q;
                    int idx = row * H_ + col;
                    float v = c[im][it][half * 2 + q] + __ldg(P.b0 + col) + __ldg(P.b1 + col);
                    float zz = P.z[idx];
                    P.out[idx] = zz * P.h[idx] + (1.f - zz) * tanhf(v);
                }
            }
        }
    }
}

// ---------------- output projection ----------------
__global__ void k_proj(const float* __restrict__ h, const float* __restrict__ Wl,
                       const float* __restrict__ bl, float* __restrict__ out) {
    int n = blockIdx.x * 8 + (threadIdx.x >> 5);
    if (n >= N_) return;
    int lane = threadIdx.x & 31;
    float4 a = *(const float4*)(h + n * H_ + lane * 4);
    float4 w = *(const float4*)(Wl + lane * 4);
    float s = a.x * w.x + a.y * w.y + a.z * w.z + a.w * w.w;
#pragma unroll
    for (int o = 16; o; o >>= 1) s += __shfl_down_sync(0xffffffffu, s, o);
    if (lane == 0) out[n] = s + bl[0];
}

// ---------------- driver ----------------
extern "C" void kernel_launch(void* const* d_in, const int* in_sizes, int n_in,
                              void* d_out, int out_size) {
    const float* x_seq = (const float*)d_in[0];
    const void*  ei    = d_in[1];
    const float* Wxz = (const float*)d_in[2];  const float* bxz = (const float*)d_in[3];
    const float* Whz = (const float*)d_in[4];  const float* bhz = (const float*)d_in[5];
    const float* Wxr = (const float*)d_in[6];  const float* bxr = (const float*)d_in[7];
    const float* Whr = (const float*)d_in[8];  const float* bhr = (const float*)d_in[9];
    const float* Wxh = (const float*)d_in[10]; const float* bxh = (const float*)d_in[11];
    const float* Whh = (const float*)d_in[12]; const float* bhh = (const float*)d_in[13];
    const float* Wl  = (const float*)d_in[14]; const float* bl  = (const float*)d_in[15];
    float* out = (float*)d_out;

    float *Tx1, *Tx2, *Th1, *Th2, *Ts1, *Ts2, *h, *z, *s, *gW;
    cudaGetSymbolAddress((void**)&Tx1, g_Tx1);
    cudaGetSymbolAddress((void**)&Tx2, g_Tx2);
    cudaGetSymbolAddress((void**)&Th1, g_Th1);
    cudaGetSymbolAddress((void**)&Th2, g_Th2);
    cudaGetSymbolAddress((void**)&Ts1, g_Ts1);
    cudaGetSymbolAddress((void**)&Ts2, g_Ts2);
    cudaGetSymbolAddress((void**)&h,   g_h);
    cudaGetSymbolAddress((void**)&z,   g_z);
    cudaGetSymbolAddress((void**)&s,   g_s);
    cudaGetSymbolAddress((void**)&gW,  g_W);

    const int ZR_SMEM = (2 * AS_WORDS + 4 * BS_WORDS) * 4;   // 55296 B
    static int attr_done = 0;
    if (!attr_done) {
        cudaFuncSetAttribute(k_gemm_zr, cudaFuncAttributeMaxDynamicSharedMemorySize, ZR_SMEM);
        attr_done = 1;
    }

    // preprocessing: 4 launches (ncu -s 5 then lands on a hot k_prop2)
    W6 w6; w6.p[0] = Wxz; w6.p[1] = Whz; w6.p[2] = Wxr; w6.p[3] = Whr; w6.p[4] = Wxh; w6.p[5] = Whh;
    k_init <<<(NH + 255) / 256, 256>>>((const int*)ei);
    k_count<<<(E_ + 255) / 256, 256>>>(ei, w6);
    k_scan <<<1, 1024>>>();
    k_fill <<<(E_ + 255) / 256, 256>>>(ei);

    const int WK = F_ * H_;
    const int GB = (N_ + 63) / 64;        // 157 row tiles

    for (int t = 0; t < T_; t++) {
        const float* xt = x_seq + (size_t)t * N_ * F_;

        k_prop2<<<dim3(N_, 2), H_>>>(xt,  Tx1, nullptr, h,   Th1, nullptr, 1.f);
        k_prop2<<<dim3(N_, 2), H_>>>(Tx1, Tx2, xt,      Th1, Th2, h,       2.f);

        GZR zr;
        const float* Axs[6] = { xt, Tx1, Tx2, h, Th1, Th2 };
        for (int i = 0; i < 6; i++) zr.A[i] = Axs[i];
        for (int k = 0; k < 3; k++) {
            zr.Bz[k] = gW + 0 * WSLICE + k * WK; zr.Bz[3 + k] = gW + 1 * WSLICE + k * WK;
            zr.Br[k] = gW + 2 * WSLICE + k * WK; zr.Br[3 + k] = gW + 3 * WSLICE + k * WK;
        }
        zr.bz0 = bxz; zr.bz1 = bhz; zr.br0 = bxr; zr.br1 = bhr;
        zr.h = h; zr.zout = z; zr.sout = s;
        k_gemm_zr<<<dim3(GB, 2), 128, ZR_SMEM>>>(zr);

        k_prop2<<<dim3(N_, 1), H_>>>(s,   Ts1, nullptr, nullptr, nullptr, nullptr, 1.f);
        k_prop2<<<dim3(N_, 1), H_>>>(Ts1, Ts2, s,       nullptr, nullptr, nullptr, 2.f);

        GP ph;
        const float* Ahs[6] = { xt, Tx1, Tx2, s, Ts1, Ts2 };
        for (int i = 0; i < 6; i++) ph.A[i] = Ahs[i];
        for (int k = 0; k < 3; k++) {
            ph.B[k] = gW + 4 * WSLICE + k * WK; ph.B[3 + k] = gW + 5 * WSLICE + k * WK;
        }
        ph.b0 = bxh; ph.b1 = bhh; ph.out = h; ph.h = h; ph.z = z;
        k_gemm_h<<<dim3(GB, 2), 128>>>(ph);

        k_proj<<<(N_ + 7) / 8, 256>>>(h, Wl, bl, out + t * N_);
    }
    (void)in_sizes; (void)n_in; (void)out_size;
}